// round 1
// baseline (speedup 1.0000x reference)
#include <cuda_runtime.h>
#include <cstdint>

// ---------------------------------------------------------------------------
// TemplatePointwiseAttention, algebraically folded:
//   A[i][h*64+j] = (1/8) * sum_c Wq[i][h*64+c] * Wk[j][h*64+c]   (128x256)
//   M[h*64+j][o] =         sum_c Wv[j][h*64+c] * Wo[h*64+c][o]   (256x128)
//   per pair p:
//     s[256]   = z[p] @ A
//     logit[h][k] = sum_j s[h*64+j] * t[k][p][j]
//     w = softmax_k(logit)
//     u[h*64+j] = sum_k w[h][k] * t[k][p][j]
//     out[p]   = u @ M + bo
// ---------------------------------------------------------------------------

#define RDIM 384
#define PTOT (RDIM * RDIM)   // 147456
#define CIN 128
#define CKV 64
#define HC  256              // H * C
#define TILE_P 128
#define THREADS 512
#define NCTAS (PTOT / TILE_P)  // 1152

typedef unsigned long long ull;

// Precomputed folded weights (fp32, L2-resident, 256 KB total)
__device__ __align__(16) float g_A[CIN * HC];   // [k=128][j=256] row-major
__device__ __align__(16) float g_M[HC * CIN];   // [k=256][o=128] row-major

// Packed fp32x2 FMA (full-rate fp32 path on Blackwell; plain FFMA is half rate)
__device__ __forceinline__ void ffma2(ull& d, ull a, ull b) {
    asm("fma.rn.f32x2 %0, %1, %2, %0;" : "+l"(d) : "l"(a), "l"(b));
}
__device__ __forceinline__ ull pack2(float x, float y) {
    ull r; asm("mov.b64 %0, {%1, %2};" : "=l"(r) : "f"(x), "f"(y)); return r;
}
__device__ __forceinline__ float2 unpack2(ull v) {
    float2 f; asm("mov.b64 {%0, %1}, %2;" : "=f"(f.x), "=f"(f.y) : "l"(v)); return f;
}

// ---------------------------------------------------------------------------
// Tiny per-launch weight-folding kernel (4.2M MAC total, ~negligible)
// ---------------------------------------------------------------------------
__global__ void __launch_bounds__(512) precompute_AM(
    const float* __restrict__ Wq, const float* __restrict__ Wk,
    const float* __restrict__ Wv, const float* __restrict__ Wo)
{
    int idx = blockIdx.x * blockDim.x + threadIdx.x;   // 0 .. 65535
    if (idx < CIN * HC) {
        int i  = idx >> 8;        // c_in row
        int jj = idx & 255;       // h*64 + j
        int h = jj >> 6, j = jj & 63;
        float s = 0.f;
        #pragma unroll 8
        for (int c = 0; c < 64; ++c)
            s += Wq[i * HC + h * 64 + c] * Wk[j * HC + h * 64 + c];
        g_A[i * HC + jj] = s * 0.125f;
    } else {
        int t  = idx - CIN * HC;  // 0 .. 32767
        int jj = t >> 7;          // h*64 + j (row of M)
        int o  = t & 127;
        int h = jj >> 6, j = jj & 63;
        float s = 0.f;
        #pragma unroll 8
        for (int c = 0; c < 64; ++c)
            s += Wv[j * HC + h * 64 + c] * Wo[(h * 64 + c) * CIN + o];
        g_M[jj * CIN + o] = s;
    }
}

// ---------------------------------------------------------------------------
// Fused main kernel. Shared memory layout (floats):
//   sZ   [    0 .. 16384)  : Z tile [128][128]
//   sSU  [16384 .. 49152)  : S then U in-place [128][256]
//   sAux [49152 .. 54272)  : GEMM weight double-buffers / per-warp t scratch
// ---------------------------------------------------------------------------
#define SZ_OFF   0
#define SSU_OFF  16384
#define SAUX_OFF 49152
#define SMEM_FLOATS (SAUX_OFF + 5120)   // 54272 floats = 217088 bytes

__global__ void __launch_bounds__(THREADS, 1) fused_tpa(
    const float* __restrict__ z2d, const float* __restrict__ t2d,
    const float* __restrict__ bo,  float* __restrict__ out)
{
    extern __shared__ float smem[];
    float* sZ   = smem + SZ_OFF;
    float* sSU  = smem + SSU_OFF;
    float* sAux = smem + SAUX_OFF;

    const int tid = threadIdx.x;
    const int p0  = blockIdx.x * TILE_P;

    // ---- Phase 0: load Z tile (contiguous 64 KB) + preload A chunk 0 ----
    {
        const float4* zg = (const float4*)(z2d + (size_t)p0 * CIN);
        float4* zs = (float4*)sZ;
        #pragma unroll
        for (int r = 0; r < 8; ++r)
            zs[r * THREADS + tid] = zg[r * THREADS + tid];
        float4 pf = *(const float4*)&g_A[tid * 4];
        *(float4*)&sAux[tid * 4] = pf;
    }
    __syncthreads();

    // ---- Phase 1: GEMM1  S[128p x 256j] = Z[128p x 128k] @ A[128k x 256j] ----
    // thread micro-tile: 8p x 8j (as 4 j-pairs), tj in [0,32), tp in [0,16)
    {
        const int tj = tid & 31;
        const int tp = tid >> 5;
        ull acc[8][4];
        #pragma unroll
        for (int i = 0; i < 8; ++i)
            #pragma unroll
            for (int m = 0; m < 4; ++m) acc[i][m] = 0ULL;

        #pragma unroll 1
        for (int c = 0; c < 16; ++c) {          // 16 chunks of 8 k
            float4 nf;
            if (c < 15) nf = *(const float4*)&g_A[(c + 1) * 2048 + tid * 4];
            const float* sWb = sAux + (c & 1) * 2048;
            const int kg = c * 8;
            #pragma unroll
            for (int k2 = 0; k2 < 4; ++k2) {    // k pairs within chunk
                float2 zv[8];
                #pragma unroll
                for (int i = 0; i < 8; ++i)
                    zv[i] = *(const float2*)&sZ[(tp * 8 + i) * CIN + kg + k2 * 2];
                #pragma unroll
                for (int sub = 0; sub < 2; ++sub) {
                    const int k = k2 * 2 + sub;
                    ull av[4];
                    #pragma unroll
                    for (int m = 0; m < 4; ++m)
                        av[m] = *(const ull*)&sWb[k * HC + tj * 2 + 64 * m];
                    #pragma unroll
                    for (int i = 0; i < 8; ++i) {
                        const float z = sub ? zv[i].y : zv[i].x;
                        const ull zd = pack2(z, z);
                        #pragma unroll
                        for (int m = 0; m < 4; ++m) ffma2(acc[i][m], zd, av[m]);
                    }
                }
            }
            if (c < 15) *(float4*)&sAux[((c + 1) & 1) * 2048 + tid * 4] = nf;
            __syncthreads();
        }
        // write S to smem
        #pragma unroll
        for (int i = 0; i < 8; ++i)
            #pragma unroll
            for (int m = 0; m < 4; ++m)
                *(ull*)&sSU[(tp * 8 + i) * HC + tj * 2 + 64 * m] = acc[i][m];
    }
    __syncthreads();

    // ---- Phase 2: logits / softmax / u  (warp-per-8-pairs) ----
    {
        const int lane = tid & 31;
        const int warp = tid >> 5;
        const int kq = lane >> 3;        // template index role (also h role later)
        const int j0 = lane & 7;
        float* sT = sAux + warp * 320;   // t scratch [4][72] + w buf at +288

        #pragma unroll 1
        for (int pl = 0; pl < 8; ++pl) {
            const int p = warp * 8 + pl;
            // cooperative, coalesced load of t[k][p][0..63] for 4 templates
            const float* tk = t2d + ((size_t)kq * PTOT + (size_t)(p0 + p)) * CKV;
            float4 ta = *(const float4*)(tk + j0 * 8);
            float4 tb = *(const float4*)(tk + j0 * 8 + 4);
            *(float4*)&sT[kq * 72 + j0 * 8]     = ta;
            *(float4*)&sT[kq * 72 + j0 * 8 + 4] = tb;
            __syncwarp();

            // logits partials: lane (kq, j0) covers j = j0 + 8i
            const float* srow = &sSU[p * HC];
            float pt0 = 0.f, pt1 = 0.f, pt2 = 0.f, pt3 = 0.f;
            #pragma unroll
            for (int i = 0; i < 8; ++i) {
                const float tv = sT[kq * 72 + j0 + 8 * i];
                pt0 += srow[0 * 64 + j0 + 8 * i] * tv;
                pt1 += srow[1 * 64 + j0 + 8 * i] * tv;
                pt2 += srow[2 * 64 + j0 + 8 * i] * tv;
                pt3 += srow[3 * 64 + j0 + 8 * i] * tv;
            }
            #pragma unroll
            for (int off = 1; off <= 4; off <<= 1) {
                pt0 += __shfl_xor_sync(0xffffffffu, pt0, off);
                pt1 += __shfl_xor_sync(0xffffffffu, pt1, off);
                pt2 += __shfl_xor_sync(0xffffffffu, pt2, off);
                pt3 += __shfl_xor_sync(0xffffffffu, pt3, off);
            }
            // softmax over templates (lanes xor 8, 16)
            float m0 = pt0, m1 = pt1, m2 = pt2, m3 = pt3;
            #pragma unroll
            for (int off = 8; off <= 16; off <<= 1) {
                m0 = fmaxf(m0, __shfl_xor_sync(0xffffffffu, m0, off));
                m1 = fmaxf(m1, __shfl_xor_sync(0xffffffffu, m1, off));
                m2 = fmaxf(m2, __shfl_xor_sync(0xffffffffu, m2, off));
                m3 = fmaxf(m3, __shfl_xor_sync(0xffffffffu, m3, off));
            }
            float e0 = __expf(pt0 - m0), e1 = __expf(pt1 - m1);
            float e2 = __expf(pt2 - m2), e3 = __expf(pt3 - m3);
            float d0 = e0, d1 = e1, d2 = e2, d3 = e3;
            #pragma unroll
            for (int off = 8; off <= 16; off <<= 1) {
                d0 += __shfl_xor_sync(0xffffffffu, d0, off);
                d1 += __shfl_xor_sync(0xffffffffu, d1, off);
                d2 += __shfl_xor_sync(0xffffffffu, d2, off);
                d3 += __shfl_xor_sync(0xffffffffu, d3, off);
            }
            if (j0 == 0) {
                sT[288 + 0 * 4 + kq] = e0 / d0;
                sT[288 + 1 * 4 + kq] = e1 / d1;
                sT[288 + 2 * 4 + kq] = e2 / d2;
                sT[288 + 3 * 4 + kq] = e3 / d3;
            }
            __syncwarp();

            // u[h*64+j] = sum_k w[h][k] * t[k][j]; lane role: hu = kq
            const int hu = kq;
            const float wk0 = sT[288 + hu * 4 + 0];
            const float wk1 = sT[288 + hu * 4 + 1];
            const float wk2 = sT[288 + hu * 4 + 2];
            const float wk3 = sT[288 + hu * 4 + 3];
            #pragma unroll
            for (int i = 0; i < 8; ++i) {
                const int jc = j0 + 8 * ((i + hu) & 7);   // stagger: bank-conflict-free STS
                float uv = wk0 * sT[0 * 72 + jc] + wk1 * sT[1 * 72 + jc]
                         + wk2 * sT[2 * 72 + jc] + wk3 * sT[3 * 72 + jc];
                sSU[p * HC + hu * 64 + jc] = uv;          // overwrite S with U in place
            }
            __syncwarp();
        }
    }
    __syncthreads();

    // ---- Phase 3: GEMM2  Out[128p x 128o] = U[128p x 256k] @ M[256k x 128o] ----
    // thread micro-tile: 4p x 8o (4 o-pairs), to in [0,16), tp2 in [0,32)
    {
        {
            float2 pf2 = *(const float2*)&g_M[tid * 2];
            *(float2*)&sAux[tid * 2] = pf2;
        }
        __syncthreads();

        const int to  = tid & 15;
        const int tp2 = tid >> 4;
        ull acc2[4][4];
        #pragma unroll
        for (int i = 0; i < 4; ++i)
            #pragma unroll
            for (int m = 0; m < 4; ++m) acc2[i][m] = 0ULL;

        #pragma unroll 1
        for (int c = 0; c < 32; ++c) {           // 32 chunks of 8 k
            float2 nf2;
            if (c < 31) nf2 = *(const float2*)&g_M[(c + 1) * 1024 + tid * 2];
            const float* sWb = sAux + (c & 1) * 1024;
            const int kg = c * 8;
            #pragma unroll
            for (int k2 = 0; k2 < 4; ++k2) {
                float2 uv[4];
                #pragma unroll
                for (int i = 0; i < 4; ++i)
                    uv[i] = *(const float2*)&sSU[(tp2 * 4 + i) * HC + kg + k2 * 2];
                #pragma unroll
                for (int sub = 0; sub < 2; ++sub) {
                    const int k = k2 * 2 + sub;
                    ull mv[4];
                    #pragma unroll
                    for (int m = 0; m < 4; ++m)
                        mv[m] = *(const ull*)&sWb[k * CIN + to * 2 + 32 * m];
                    #pragma unroll
                    for (int i = 0; i < 4; ++i) {
                        const float u = sub ? uv[i].y : uv[i].x;
                        const ull ud = pack2(u, u);
                        #pragma unroll
                        for (int m = 0; m < 4; ++m) ffma2(acc2[i][m], ud, mv[m]);
                    }
                }
            }
            if (c < 31) *(float2*)&sAux[((c + 1) & 1) * 1024 + tid * 2] = nf2;
            __syncthreads();
        }

        // epilogue: + bo, write out (coalesced float2)
        float2 bo2[4];
        #pragma unroll
        for (int m = 0; m < 4; ++m) bo2[m] = *(const float2*)&bo[to * 2 + 32 * m];
        #pragma unroll
        for (int i = 0; i < 4; ++i) {
            float* orow = out + (size_t)(p0 + tp2 * 4 + i) * CIN;
            #pragma unroll
            for (int m = 0; m < 4; ++m) {
                float2 v = unpack2(acc2[i][m]);
                v.x += bo2[m].x;
                v.y += bo2[m].y;
                *(float2*)&orow[to * 2 + 32 * m] = v;
            }
        }
    }
}

// ---------------------------------------------------------------------------
extern "C" void kernel_launch(void* const* d_in, const int* in_sizes, int n_in,
                              void* d_out, int out_size)
{
    const float* z2d = (const float*)d_in[0];   // [1,384,384,128]
    const float* t2d = (const float*)d_in[1];   // [1,4,384,384,64]
    const float* Wq  = (const float*)d_in[2];   // [128,256]
    const float* Wk  = (const float*)d_in[3];   // [64,256]
    const float* Wv  = (const float*)d_in[4];   // [64,256]
    const float* Wo  = (const float*)d_in[5];   // [256,128]
    const float* bo  = (const float*)d_in[6];   // [128]
    float* out = (float*)d_out;                 // [1,384,384,128]

    precompute_AM<<<128, 512>>>(Wq, Wk, Wv, Wo);

    const size_t smem_bytes = (size_t)SMEM_FLOATS * sizeof(float);
    cudaFuncSetAttribute(fused_tpa, cudaFuncAttributeMaxDynamicSharedMemorySize,
                         (int)smem_bytes);
    fused_tpa<<<NCTAS, THREADS, smem_bytes>>>(z2d, t2d, bo, out);
}

// round 2
// speedup vs baseline: 1.0018x; 1.0018x over previous
#include <cuda_runtime.h>
#include <cstdint>

// ---------------------------------------------------------------------------
// TemplatePointwiseAttention, algebraically folded:
//   A[i][h*64+j] = (1/8) * sum_c Wq[i][h*64+c] * Wk[j][h*64+c]   (128x256)
//   M[h*64+j][o] =         sum_c Wv[j][h*64+c] * Wo[h*64+c][o]   (256x128)
//   per pair p:
//     s[256]   = z[p] @ A
//     logit[h][k] = sum_j s[h*64+j] * t[k][p][j]
//     w = softmax_k(logit)
//     u[h*64+j] = sum_k w[h][k] * t[k][p][j]
//     out[p]   = u @ M + bo
// ---------------------------------------------------------------------------

#define RDIM 384
#define PTOT (RDIM * RDIM)   // 147456
#define CIN 128
#define CKV 64
#define HC  256              // H * C
#define TILE_P 128
#define THREADS 512
#define NCTAS (PTOT / TILE_P)  // 1152

typedef unsigned long long ull;

// Precomputed folded weights (fp32, L2-resident, 256 KB total)
__device__ __align__(16) float g_A[CIN * HC];   // [k=128][j=256] row-major
__device__ __align__(16) float g_M[HC * CIN];   // [k=256][o=128] row-major

// Packed fp32x2 FMA (full-rate fp32 path on Blackwell; plain FFMA is half rate)
__device__ __forceinline__ void ffma2(ull& d, ull a, ull b) {
    asm("fma.rn.f32x2 %0, %1, %2, %0;" : "+l"(d) : "l"(a), "l"(b));
}
__device__ __forceinline__ ull pack2(float x, float y) {
    ull r; asm("mov.b64 %0, {%1, %2};" : "=l"(r) : "f"(x), "f"(y)); return r;
}
__device__ __forceinline__ float2 unpack2(ull v) {
    float2 f; asm("mov.b64 {%0, %1}, %2;" : "=f"(f.x), "=f"(f.y) : "l"(v)); return f;
}

// ---------------------------------------------------------------------------
// Tiny per-launch weight-folding kernel (4.2M MAC total, ~negligible)
// ---------------------------------------------------------------------------
__global__ void __launch_bounds__(512) precompute_AM(
    const float* __restrict__ Wq, const float* __restrict__ Wk,
    const float* __restrict__ Wv, const float* __restrict__ Wo)
{
    int idx = blockIdx.x * blockDim.x + threadIdx.x;   // 0 .. 65535
    if (idx < CIN * HC) {
        int i  = idx >> 8;        // c_in row
        int jj = idx & 255;       // h*64 + j
        int h = jj >> 6, j = jj & 63;
        float s = 0.f;
        #pragma unroll 8
        for (int c = 0; c < 64; ++c)
            s += Wq[i * HC + h * 64 + c] * Wk[j * HC + h * 64 + c];
        g_A[i * HC + jj] = s * 0.125f;
    } else {
        int t  = idx - CIN * HC;  // 0 .. 32767
        int jj = t >> 7;          // h*64 + j (row of M)
        int o  = t & 127;
        int h = jj >> 6, j = jj & 63;
        float s = 0.f;
        #pragma unroll 8
        for (int c = 0; c < 64; ++c)
            s += Wv[j * HC + h * 64 + c] * Wo[(h * 64 + c) * CIN + o];
        g_M[jj * CIN + o] = s;
    }
}

// ---------------------------------------------------------------------------
// Fused main kernel. Shared memory layout (floats):
//   sZ   [    0 .. 16384)  : Z tile [128][128]
//   sSU  [16384 .. 49152)  : S then U in-place [128][256]
//   sAux [49152 .. 54272)  : GEMM weight double-buffers / per-warp t scratch
// ---------------------------------------------------------------------------
#define SZ_OFF   0
#define SSU_OFF  16384
#define SAUX_OFF 49152
#define SMEM_FLOATS (SAUX_OFF + 5120)   // 54272 floats = 217088 bytes

__global__ void __launch_bounds__(THREADS, 1) fused_tpa(
    const float* __restrict__ z2d, const float* __restrict__ t2d,
    const float* __restrict__ bo,  float* __restrict__ out)
{
    extern __shared__ float smem[];
    float* sZ   = smem + SZ_OFF;
    float* sSU  = smem + SSU_OFF;
    float* sAux = smem + SAUX_OFF;

    const int tid = threadIdx.x;
    const int p0  = blockIdx.x * TILE_P;

    // ---- Phase 0: load Z tile (contiguous 64 KB) + preload A chunk 0 ----
    {
        const float4* zg = (const float4*)(z2d + (size_t)p0 * CIN);
        float4* zs = (float4*)sZ;
        #pragma unroll
        for (int r = 0; r < 8; ++r)
            zs[r * THREADS + tid] = zg[r * THREADS + tid];
        float4 pf = *(const float4*)&g_A[tid * 4];
        *(float4*)&sAux[tid * 4] = pf;
    }
    __syncthreads();

    // ---- Phase 1: GEMM1  S[128p x 256j] = Z[128p x 128k] @ A[128k x 256j] ----
    // thread micro-tile: 8p x 8j (as 4 j-pairs), tj in [0,32), tp in [0,16)
    {
        const int tj = tid & 31;
        const int tp = tid >> 5;
        ull acc[8][4];
        #pragma unroll
        for (int i = 0; i < 8; ++i)
            #pragma unroll
            for (int m = 0; m < 4; ++m) acc[i][m] = 0ULL;

        #pragma unroll 1
        for (int c = 0; c < 16; ++c) {          // 16 chunks of 8 k
            float4 nf;
            if (c < 15) nf = *(const float4*)&g_A[(c + 1) * 2048 + tid * 4];
            const float* sWb = sAux + (c & 1) * 2048;
            const int kg = c * 8;
            #pragma unroll
            for (int k2 = 0; k2 < 4; ++k2) {    // k pairs within chunk
                float2 zv[8];
                #pragma unroll
                for (int i = 0; i < 8; ++i)
                    zv[i] = *(const float2*)&sZ[(tp * 8 + i) * CIN + kg + k2 * 2];
                #pragma unroll
                for (int sub = 0; sub < 2; ++sub) {
                    const int k = k2 * 2 + sub;
                    ull av[4];
                    #pragma unroll
                    for (int m = 0; m < 4; ++m)
                        av[m] = *(const ull*)&sWb[k * HC + tj * 2 + 64 * m];
                    #pragma unroll
                    for (int i = 0; i < 8; ++i) {
                        const float z = sub ? zv[i].y : zv[i].x;
                        const ull zd = pack2(z, z);
                        #pragma unroll
                        for (int m = 0; m < 4; ++m) ffma2(acc[i][m], zd, av[m]);
                    }
                }
            }
            if (c < 15) *(float4*)&sAux[((c + 1) & 1) * 2048 + tid * 4] = nf;
            __syncthreads();
        }
        // write S to smem
        #pragma unroll
        for (int i = 0; i < 8; ++i)
            #pragma unroll
            for (int m = 0; m < 4; ++m)
                *(ull*)&sSU[(tp * 8 + i) * HC + tj * 2 + 64 * m] = acc[i][m];
    }
    __syncthreads();

    // ---- Phase 2: logits / softmax / u  (warp-per-8-pairs) ----
    {
        const int lane = tid & 31;
        const int warp = tid >> 5;
        const int kq = lane >> 3;        // template index role (also h role later)
        const int j0 = lane & 7;
        float* sT = sAux + warp * 320;   // t scratch [4][72] + w buf at +288

        #pragma unroll 1
        for (int pl = 0; pl < 8; ++pl) {
            const int p = warp * 8 + pl;
            // cooperative, coalesced load of t[k][p][0..63] for 4 templates
            const float* tk = t2d + ((size_t)kq * PTOT + (size_t)(p0 + p)) * CKV;
            float4 ta = *(const float4*)(tk + j0 * 8);
            float4 tb = *(const float4*)(tk + j0 * 8 + 4);
            *(float4*)&sT[kq * 72 + j0 * 8]     = ta;
            *(float4*)&sT[kq * 72 + j0 * 8 + 4] = tb;
            __syncwarp();

            // logits partials: lane (kq, j0) covers j = j0 + 8i
            const float* srow = &sSU[p * HC];
            float pt0 = 0.f, pt1 = 0.f, pt2 = 0.f, pt3 = 0.f;
            #pragma unroll
            for (int i = 0; i < 8; ++i) {
                const float tv = sT[kq * 72 + j0 + 8 * i];
                pt0 += srow[0 * 64 + j0 + 8 * i] * tv;
                pt1 += srow[1 * 64 + j0 + 8 * i] * tv;
                pt2 += srow[2 * 64 + j0 + 8 * i] * tv;
                pt3 += srow[3 * 64 + j0 + 8 * i] * tv;
            }
            #pragma unroll
            for (int off = 1; off <= 4; off <<= 1) {
                pt0 += __shfl_xor_sync(0xffffffffu, pt0, off);
                pt1 += __shfl_xor_sync(0xffffffffu, pt1, off);
                pt2 += __shfl_xor_sync(0xffffffffu, pt2, off);
                pt3 += __shfl_xor_sync(0xffffffffu, pt3, off);
            }
            // softmax over templates (lanes xor 8, 16)
            float m0 = pt0, m1 = pt1, m2 = pt2, m3 = pt3;
            #pragma unroll
            for (int off = 8; off <= 16; off <<= 1) {
                m0 = fmaxf(m0, __shfl_xor_sync(0xffffffffu, m0, off));
                m1 = fmaxf(m1, __shfl_xor_sync(0xffffffffu, m1, off));
                m2 = fmaxf(m2, __shfl_xor_sync(0xffffffffu, m2, off));
                m3 = fmaxf(m3, __shfl_xor_sync(0xffffffffu, m3, off));
            }
            float e0 = __expf(pt0 - m0), e1 = __expf(pt1 - m1);
            float e2 = __expf(pt2 - m2), e3 = __expf(pt3 - m3);
            float d0 = e0, d1 = e1, d2 = e2, d3 = e3;
            #pragma unroll
            for (int off = 8; off <= 16; off <<= 1) {
                d0 += __shfl_xor_sync(0xffffffffu, d0, off);
                d1 += __shfl_xor_sync(0xffffffffu, d1, off);
                d2 += __shfl_xor_sync(0xffffffffu, d2, off);
                d3 += __shfl_xor_sync(0xffffffffu, d3, off);
            }
            if (j0 == 0) {
                sT[288 + 0 * 4 + kq] = e0 / d0;
                sT[288 + 1 * 4 + kq] = e1 / d1;
                sT[288 + 2 * 4 + kq] = e2 / d2;
                sT[288 + 3 * 4 + kq] = e3 / d3;
            }
            __syncwarp();

            // u[h*64+j] = sum_k w[h][k] * t[k][j]; lane role: hu = kq
            const int hu = kq;
            const float wk0 = sT[288 + hu * 4 + 0];
            const float wk1 = sT[288 + hu * 4 + 1];
            const float wk2 = sT[288 + hu * 4 + 2];
            const float wk3 = sT[288 + hu * 4 + 3];
            #pragma unroll
            for (int i = 0; i < 8; ++i) {
                const int jc = j0 + 8 * ((i + hu) & 7);   // stagger: bank-conflict-free STS
                float uv = wk0 * sT[0 * 72 + jc] + wk1 * sT[1 * 72 + jc]
                         + wk2 * sT[2 * 72 + jc] + wk3 * sT[3 * 72 + jc];
                sSU[p * HC + hu * 64 + jc] = uv;          // overwrite S with U in place
            }
            __syncwarp();
        }
    }
    __syncthreads();

    // ---- Phase 3: GEMM2  Out[128p x 128o] = U[128p x 256k] @ M[256k x 128o] ----
    // thread micro-tile: 4p x 8o (4 o-pairs), to in [0,16), tp2 in [0,32)
    {
        {
            float2 pf2 = *(const float2*)&g_M[tid * 2];
            *(float2*)&sAux[tid * 2] = pf2;
        }
        __syncthreads();

        const int to  = tid & 15;
        const int tp2 = tid >> 4;
        ull acc2[4][4];
        #pragma unroll
        for (int i = 0; i < 4; ++i)
            #pragma unroll
            for (int m = 0; m < 4; ++m) acc2[i][m] = 0ULL;

        #pragma unroll 1
        for (int c = 0; c < 32; ++c) {           // 32 chunks of 8 k
            float2 nf2;
            if (c < 31) nf2 = *(const float2*)&g_M[(c + 1) * 1024 + tid * 2];
            const float* sWb = sAux + (c & 1) * 1024;
            const int kg = c * 8;
            #pragma unroll
            for (int k2 = 0; k2 < 4; ++k2) {
                float2 uv[4];
                #pragma unroll
                for (int i = 0; i < 4; ++i)
                    uv[i] = *(const float2*)&sSU[(tp2 * 4 + i) * HC + kg + k2 * 2];
                #pragma unroll
                for (int sub = 0; sub < 2; ++sub) {
                    const int k = k2 * 2 + sub;
                    ull mv[4];
                    #pragma unroll
                    for (int m = 0; m < 4; ++m)
                        mv[m] = *(const ull*)&sWb[k * CIN + to * 2 + 32 * m];
                    #pragma unroll
                    for (int i = 0; i < 4; ++i) {
                        const float u = sub ? uv[i].y : uv[i].x;
                        const ull ud = pack2(u, u);
                        #pragma unroll
                        for (int m = 0; m < 4; ++m) ffma2(acc2[i][m], ud, mv[m]);
                    }
                }
            }
            if (c < 31) *(float2*)&sAux[((c + 1) & 1) * 1024 + tid * 2] = nf2;
            __syncthreads();
        }

        // epilogue: + bo, write out (coalesced float2)
        float2 bo2[4];
        #pragma unroll
        for (int m = 0; m < 4; ++m) bo2[m] = *(const float2*)&bo[to * 2 + 32 * m];
        #pragma unroll
        for (int i = 0; i < 4; ++i) {
            float* orow = out + (size_t)(p0 + tp2 * 4 + i) * CIN;
            #pragma unroll
            for (int m = 0; m < 4; ++m) {
                float2 v = unpack2(acc2[i][m]);
                v.x += bo2[m].x;
                v.y += bo2[m].y;
                *(float2*)&orow[to * 2 + 32 * m] = v;
            }
        }
    }
}

// ---------------------------------------------------------------------------
extern "C" void kernel_launch(void* const* d_in, const int* in_sizes, int n_in,
                              void* d_out, int out_size)
{
    const float* z2d = (const float*)d_in[0];   // [1,384,384,128]
    const float* t2d = (const float*)d_in[1];   // [1,4,384,384,64]
    const float* Wq  = (const float*)d_in[2];   // [128,256]
    const float* Wk  = (const float*)d_in[3];   // [64,256]
    const float* Wv  = (const float*)d_in[4];   // [64,256]
    const float* Wo  = (const float*)d_in[5];   // [256,128]
    const float* bo  = (const float*)d_in[6];   // [128]
    float* out = (float*)d_out;                 // [1,384,384,128]

    precompute_AM<<<128, 512>>>(Wq, Wk, Wv, Wo);

    const size_t smem_bytes = (size_t)SMEM_FLOATS * sizeof(float);
    cudaFuncSetAttribute(fused_tpa, cudaFuncAttributeMaxDynamicSharedMemorySize,
                         (int)smem_bytes);
    fused_tpa<<<NCTAS, THREADS, smem_bytes>>>(z2d, t2d, bo, out);
}